// round 9
// baseline (speedup 1.0000x reference)
#include <cuda_runtime.h>
#include <cuda_bf16.h>
#include <cstdint>

#define NS   32768
#define NA   2048
#define ASZ  1024
#define KSP  64
#define NB   4
#define NEG_INF (-3.4e38f)
#define CAND_MAX 65536
#define NTILES   4096          // exact 128x128 tiles per batch (16 x 256)
#define NT2      2048          // approx 128x256 tiles per batch (16 x 128)
#define EPS_TOTAL 1.0f         // >= 2*eps for bf16 tile-max error

#define SIG_PAD  512
#define SIG_LEN  33792

typedef unsigned long long ull;

// ---------------- static scratch (~6.5 MB) ----------------
__device__ __align__(16) __nv_bfloat16 g_atoms_bf[(size_t)NA * ASZ];   // 4 MB
__device__ __align__(16) __nv_bfloat16 g_sig8[NB][8][SIG_LEN];         // 2.1 MB
__device__ float    g_tilemax[NB * NT2];
__device__ float    g_thresh[NB];
__device__ unsigned g_work[NB][NTILES];
__device__ unsigned g_work_cnt[NB];
__device__ float    g_cand_val[NB][CAND_MAX];
__device__ unsigned g_cand_idx[NB][CAND_MAX];
__device__ unsigned g_cand_cnt[NB];
__device__ float    g_topv[NB * KSP];
__device__ unsigned g_topi[NB * KSP];

__device__ __forceinline__ uint32_t smem_u32(const void* p) {
    uint32_t a;
    asm("{ .reg .u64 t; cvta.to.shared.u64 t, %1; cvt.u32.u64 %0, t; }" : "=r"(a) : "l"(p));
    return a;
}
#define CP_ASYNC16(dst, src) \
    asm volatile("cp.async.cg.shared.global [%0], [%1], 16;" :: "r"(dst), "l"(src))
#define CP_COMMIT() asm volatile("cp.async.commit_group;" ::: "memory")
#define CP_WAIT(n)  asm volatile("cp.async.wait_group %0;" :: "n"(n) : "memory")

// ---------------- init / prepass ----------------
__global__ void init_kernel() {
    int i = blockIdx.x * blockDim.x + threadIdx.x;
    if (i < NB) { g_cand_cnt[i] = 0u; g_work_cnt[i] = 0u; }
}
__global__ void conv_atoms_kernel(const float* __restrict__ atoms) {
    size_t i = (size_t)blockIdx.x * blockDim.x + threadIdx.x;
    if (i < (size_t)NA * ASZ) g_atoms_bf[i] = __float2bfloat16_rn(atoms[i]);
}
__global__ void build_sig_kernel(const float* __restrict__ orig) {
    size_t i = (size_t)blockIdx.x * blockDim.x + threadIdx.x;
    if (i >= (size_t)NB * 8 * SIG_LEN) return;
    int j = (int)(i % SIG_LEN);
    int c = (int)((i / SIG_LEN) % 8);
    int b = (int)(i / ((size_t)8 * SIG_LEN));
    int s = j - SIG_PAD + c;
    g_sig8[b][c][j] = (s >= 0 && s < NS) ? __float2bfloat16_rn(orig[(size_t)b * NS + s])
                                         : __float2bfloat16_rn(0.f);
}

// ---------------- pass 1: bf16 mma.sync correlation, tile-max only ----------------
// CTA tile: 128 atoms x 256 times, K=1024 in chunks of 32. 512 threads, 16 warps in
// 4(m) x 4(n) grid, each warp m32 x n64 = 2 m16-frags x 8 n8-frags (64 accumulators).
// 4-stage cp.async pipeline, one __syncthreads per chunk.
//
// smem per stage (24 KB): A 8 KB [m16b(8)][kb(2)][slot(32)][16B], slot=(r&15)|(h<<4)
//                         B 16 KB [kb(2)][n8b(32)][slot(16)][16B], slot=(t&7)|(h<<3)
#define NSTAGE 4
#define STAGE_BYTES 24576
__global__ __launch_bounds__(512, 1)
void corr_tc_kernel() {
    extern __shared__ __align__(128) unsigned char smem[];
    float* s_wmax = (float*)(smem + NSTAGE * STAGE_BYTES);

    const int b  = blockIdx.z;
    const int a0 = blockIdx.y << 7;
    const int t0 = blockIdx.x << 8;
    const int tid = threadIdx.x;
    const int w = tid >> 5, lane = tid & 31;
    const int wm = w & 3, wn = w >> 2;

    uint32_t sAu[NSTAGE], sBu[NSTAGE];
#pragma unroll
    for (int s = 0; s < NSTAGE; s++) {
        sAu[s] = smem_u32(smem + s * STAGE_BYTES);
        sBu[s] = sAu[s] + 8192;
    }

    float acc[2][8][4];
#pragma unroll
    for (int mi = 0; mi < 2; mi++)
#pragma unroll
        for (int ni = 0; ni < 8; ni++)
#pragma unroll
            for (int r = 0; r < 4; r++) acc[mi][ni][r] = 0.f;

    // async fill of one 32-K chunk into stage `buf`
    auto fill = [&](int ck, int buf) {
        const int kk = ck << 5;
        {   // A: 512 x 16B items, 1 per thread
            int r = tid >> 2, c8 = tid & 3;
            int m16b = r >> 4, kb = c8 >> 1, h = c8 & 1;
            int slot = (r & 15) | (h << 4);
            uint32_t off = (uint32_t)(((((m16b << 1) | kb) << 5) | slot) << 4);
            CP_ASYNC16(sAu[buf] + off,
                       (const void*)(g_atoms_bf + (size_t)(a0 + r) * ASZ + kk + (c8 << 3)));
        }
        // B: 1024 x 16B items, 2 per thread
#pragma unroll
        for (int q = 0; q < 2; q++) {
            int i = tid + (q << 9);
            int t = i >> 2, c8 = i & 3;
            int n8b = t >> 3, kb = c8 >> 1, h = c8 & 1;
            int slot = (t & 7) | (h << 3);
            int c = t & 7;
            uint32_t off = (uint32_t)(((((kb << 5) | n8b) << 4) | slot) << 4);
            CP_ASYNC16(sBu[buf] + off,
                       (const void*)(&g_sig8[b][c][t0 + t + kk + (c8 << 3) - c]));
        }
    };

    fill(0, 0); CP_COMMIT();
    fill(1, 1); CP_COMMIT();
    fill(2, 2); CP_COMMIT();

    for (int ck = 0; ck < 32; ck++) {
        // ensure group `ck` retired: issued so far = min(32, ck+3) groups
        if (ck < 29) { CP_WAIT(2); } else { CP_WAIT(0); }
        __syncthreads();
        if (ck + 3 < 32) { fill(ck + 3, (ck + 3) & (NSTAGE - 1)); CP_COMMIT(); }

        const int p = ck & (NSTAGE - 1);
        const uint32_t sAp = sAu[p], sBp = sBu[p];
#pragma unroll
        for (int kb = 0; kb < 2; kb++) {
            uint32_t a[2][4];
#pragma unroll
            for (int mi = 0; mi < 2; mi++) {
                uint32_t addr = sAp + (uint32_t)((((((wm << 1) | mi) << 1) | kb) << 9) | (lane << 4));
                asm volatile("ldmatrix.sync.aligned.m8n8.x4.shared.b16 {%0,%1,%2,%3}, [%4];"
                    : "=r"(a[mi][0]), "=r"(a[mi][1]), "=r"(a[mi][2]), "=r"(a[mi][3]) : "r"(addr));
            }
#pragma unroll
            for (int jj = 0; jj < 4; jj++) {
                uint32_t bf[2][2];
                uint32_t addr = sBp + (uint32_t)((((kb << 5) | ((wn << 3) + (jj << 1))) << 8) | (lane << 4));
                asm volatile("ldmatrix.sync.aligned.m8n8.x4.shared.b16 {%0,%1,%2,%3}, [%4];"
                    : "=r"(bf[0][0]), "=r"(bf[0][1]), "=r"(bf[1][0]), "=r"(bf[1][1]) : "r"(addr));
#pragma unroll
                for (int mi = 0; mi < 2; mi++)
#pragma unroll
                    for (int nn = 0; nn < 2; nn++)
                        asm volatile(
                            "mma.sync.aligned.m16n8k16.row.col.f32.bf16.bf16.f32 "
                            "{%0,%1,%2,%3}, {%4,%5,%6,%7}, {%8,%9}, {%0,%1,%2,%3};"
                            : "+f"(acc[mi][(jj << 1) + nn][0]), "+f"(acc[mi][(jj << 1) + nn][1]),
                              "+f"(acc[mi][(jj << 1) + nn][2]), "+f"(acc[mi][(jj << 1) + nn][3])
                            : "r"(a[mi][0]), "r"(a[mi][1]), "r"(a[mi][2]), "r"(a[mi][3]),
                              "r"(bf[nn][0]), "r"(bf[nn][1]));
            }
        }
        __syncthreads();
    }

    // epilogue: per-thread max over 64 accs -> warp -> CTA -> g_tilemax
    float m = NEG_INF;
#pragma unroll
    for (int mi = 0; mi < 2; mi++)
#pragma unroll
        for (int ni = 0; ni < 8; ni++)
#pragma unroll
            for (int r = 0; r < 4; r++) m = fmaxf(m, acc[mi][ni][r]);
#pragma unroll
    for (int o = 16; o > 0; o >>= 1) m = fmaxf(m, __shfl_xor_sync(0xffffffffu, m, o));
    if (lane == 0) s_wmax[w] = m;
    __syncthreads();
    if (tid == 0) {
        float mm = s_wmax[0];
#pragma unroll
        for (int i = 1; i < 16; i++) mm = fmaxf(mm, s_wmax[i]);
        g_tilemax[b * NT2 + blockIdx.y * 128 + blockIdx.x] = mm;
    }
}

// ---------------- threshold: (64th-largest approx tile max) - EPS ----------------
__global__ void thresh_kernel() {
    __shared__ float sv[NT2];
    __shared__ float rv[256];
    __shared__ int   ri[256];
    const int b = blockIdx.x, tid = threadIdx.x;
    for (int i = tid; i < NT2; i += 256) sv[i] = g_tilemax[b * NT2 + i];
    __syncthreads();
    for (int it = 0; it < KSP; it++) {
        float best = NEG_INF; int bi = 0;
        for (int i = tid; i < NT2; i += 256)
            if (sv[i] > best) { best = sv[i]; bi = i; }
        rv[tid] = best; ri[tid] = bi;
        __syncthreads();
        for (int s = 128; s > 0; s >>= 1) {
            if (tid < s && rv[tid + s] > rv[tid]) { rv[tid] = rv[tid + s]; ri[tid] = ri[tid + s]; }
            __syncthreads();
        }
        if (tid == 0) {
            if (it == KSP - 1) g_thresh[b] = rv[0] - EPS_TOTAL;
            sv[ri[0]] = NEG_INF;
        }
        __syncthreads();
    }
}

// ---------------- worklist: hot 128x256 approx tiles -> 2 exact 128x128 tiles ----------------
__global__ void worklist_kernel() {
    const int b = blockIdx.x;
    const float tau = g_thresh[b];
    for (int i = threadIdx.x; i < NT2; i += blockDim.x) {
        if (g_tilemax[b * NT2 + i] >= tau) {
            int abk = i >> 7, t2 = i & 127;
            unsigned p = atomicAdd(&g_work_cnt[b], 2u);
            g_work[b][p]     = (unsigned)(abk * 256 + 2 * t2);
            g_work[b][p + 1] = (unsigned)(abk * 256 + 2 * t2 + 1);
        }
    }
}

// ---------------- exact fp32 tile GEMM (validated R3 core, f32x2 packed) ----------------
__device__ __forceinline__ float f32x2_lo(ull v) { return __uint_as_float((unsigned)(v & 0xffffffffull)); }
__device__ __forceinline__ float f32x2_hi(ull v) { return __uint_as_float((unsigned)(v >> 32)); }

__device__ __forceinline__ void tile_gemm(
    const float* __restrict__ ob, const float* __restrict__ atoms,
    int a0, int t0, int tid, ull acc2[4][8],
    float (*As)[132], float* Bs)
{
    const int tx = tid & 15, ty = tid >> 4;
    const int kload = tid & 15, sload = tid >> 4;
#pragma unroll
    for (int i2 = 0; i2 < 4; i2++)
#pragma unroll
        for (int j = 0; j < 8; j++) acc2[i2][j] = 0ull;

    for (int kk = 0; kk < ASZ; kk += 16) {
#pragma unroll
        for (int i = 0; i < 8; i++) {
            int a = (i << 4) + sload;
            As[kload][a] = atoms[(size_t)(a0 + a) * ASZ + kk + kload];
        }
        if (tid < 160) {
            int src = t0 + kk - 512 + tid;
            Bs[tid] = (src >= 0 && src < NS) ? ob[src] : 0.f;
        }
        __syncthreads();

        unsigned br[24];
#pragma unroll
        for (int q = 0; q < 6; q++) {
            float4 v = *(const float4*)&Bs[(tx << 3) + (q << 2)];
            br[q * 4 + 0] = __float_as_uint(v.x); br[q * 4 + 1] = __float_as_uint(v.y);
            br[q * 4 + 2] = __float_as_uint(v.z); br[q * 4 + 3] = __float_as_uint(v.w);
        }
#pragma unroll
        for (int k = 0; k < 16; k++) {
            ull ar2[4];
#pragma unroll
            for (int i2 = 0; i2 < 4; i2++)
                ar2[i2] = *(const ull*)&As[k][(ty << 3) + (i2 << 1)];
#pragma unroll
            for (int j = 0; j < 8; j++) {
                ull bb;
                asm("mov.b64 %0, {%1, %1};" : "=l"(bb) : "r"(br[k + j]));
#pragma unroll
                for (int i2 = 0; i2 < 4; i2++)
                    asm("fma.rn.f32x2 %0, %1, %2, %0;"
                        : "+l"(acc2[i2][j]) : "l"(ar2[i2]), "l"(bb));
            }
        }
        __syncthreads();
    }
}

// ---------------- pass 2: exact recompute of hot tiles, compact candidates ----------------
__global__ __launch_bounds__(256, 2)
void recompute_kernel(const float* __restrict__ orig, const float* __restrict__ atoms) {
    __shared__ float As[16][132];
    __shared__ float Bs[160];
    const int b = blockIdx.y;
    const float tau = g_thresh[b];
    const unsigned cnt = g_work_cnt[b];
    const int tid = threadIdx.x;
    const int tx = tid & 15, ty = tid >> 4;

    for (unsigned w = blockIdx.x; w < cnt; w += gridDim.x) {
        unsigned tile = g_work[b][w];
        int a0 = (int)(tile >> 8) << 7;          // tile = atom_blk*256 + time_blk
        int t0 = (int)(tile & 255u) << 7;
        ull acc2[4][8];
        tile_gemm(orig + (size_t)b * NS, atoms, a0, t0, tid, acc2, As, Bs);

#pragma unroll
        for (int i2 = 0; i2 < 4; i2++) {
#pragma unroll
            for (int j = 0; j < 8; j++) {
                float vlo = f32x2_lo(acc2[i2][j]);
                float vhi = f32x2_hi(acc2[i2][j]);
                int abase = a0 + (ty << 3) + (i2 << 1);
                int t = t0 + (tx << 3) + j;
                if (vlo >= tau) {
                    unsigned pos = atomicAdd(&g_cand_cnt[b], 1u);
                    if (pos < CAND_MAX) {
                        g_cand_val[b][pos] = vlo;
                        g_cand_idx[b][pos] = (unsigned)abase * (unsigned)NS + (unsigned)t;
                    }
                }
                if (vhi >= tau) {
                    unsigned pos = atomicAdd(&g_cand_cnt[b], 1u);
                    if (pos < CAND_MAX) {
                        g_cand_val[b][pos] = vhi;
                        g_cand_idx[b][pos] = (unsigned)(abase + 1) * (unsigned)NS + (unsigned)t;
                    }
                }
            }
        }
        __syncthreads();
    }
}

// ---------------- exact top-64 among candidates ----------------
__global__ void select_kernel() {
    __shared__ float rv[256];
    __shared__ int   ri[256];
    const int b = blockIdx.x, tid = threadIdx.x;
    unsigned n = g_cand_cnt[b];
    if (n > CAND_MAX) n = CAND_MAX;
    for (int it = 0; it < KSP; it++) {
        float best = NEG_INF; int bi = 0;
        for (unsigned i = tid; i < n; i += 256) {
            float v = g_cand_val[b][i];
            if (v > best) { best = v; bi = (int)i; }
        }
        rv[tid] = best; ri[tid] = bi;
        __syncthreads();
        for (int s = 128; s > 0; s >>= 1) {
            if (tid < s && rv[tid + s] > rv[tid]) { rv[tid] = rv[tid + s]; ri[tid] = ri[tid + s]; }
            __syncthreads();
        }
        if (tid == 0) {
            g_topv[b * KSP + it] = rv[0];
            g_topi[b * KSP + it] = g_cand_idx[b][ri[0]];
            g_cand_val[b][ri[0]] = NEG_INF;
        }
        __syncthreads();
    }
}

// ---------------- reconstruction: deterministic gather ----------------
__global__ void output_kernel(const float* __restrict__ atoms, float* __restrict__ out) {
    __shared__ float sv[KSP];
    __shared__ int   sa[KSP];
    __shared__ int   st[KSP];
    const int b = blockIdx.y, tid = threadIdx.x;
    if (tid < KSP) {
        sv[tid] = g_topv[b * KSP + tid];
        unsigned idx = g_topi[b * KSP + tid];
        sa[tid] = (int)(idx / (unsigned)NS);
        st[tid] = (int)(idx % (unsigned)NS);
    }
    __syncthreads();
    const int p = blockIdx.x * blockDim.x + tid;
    float acc = 0.f;
#pragma unroll 8
    for (int j = 0; j < KSP; j++) {
        int o = p - st[j];
        if ((unsigned)o < (unsigned)ASZ) acc += atoms[(size_t)sa[j] * ASZ + o] * sv[j];
    }
    out[(size_t)b * NS + p] = acc;
}

// ---------------- launch ----------------
extern "C" void kernel_launch(void* const* d_in, const int* in_sizes, int n_in,
                              void* d_out, int out_size) {
    const float* orig  = (const float*)d_in[0];
    const float* atoms = (const float*)d_in[1];
    if (n_in >= 2 && in_sizes[0] == NA * ASZ) {   // defensive operand-order check
        const float* t = orig; orig = atoms; atoms = t;
    }
    float* out = (float*)d_out;

    const int CORR_SMEM = NSTAGE * STAGE_BYTES + 128;   // 96 KB stages + wmax
    cudaFuncSetAttribute(corr_tc_kernel, cudaFuncAttributeMaxDynamicSharedMemorySize, CORR_SMEM);

    init_kernel<<<1, 32>>>();
    conv_atoms_kernel<<<(NA * ASZ + 255) / 256, 256>>>(atoms);
    build_sig_kernel<<<(NB * 8 * SIG_LEN + 255) / 256, 256>>>(orig);
    corr_tc_kernel<<<dim3(128, 16, NB), 512, CORR_SMEM>>>();
    thresh_kernel<<<NB, 256>>>();
    worklist_kernel<<<NB, 256>>>();
    recompute_kernel<<<dim3(256, NB), 256>>>(orig, atoms);
    select_kernel<<<NB, 256>>>();
    output_kernel<<<dim3(NS / 256, NB), 256>>>(atoms, out);
}

// round 12
// speedup vs baseline: 1.1737x; 1.1737x over previous
#include <cuda_runtime.h>
#include <cuda_bf16.h>
#include <cstdint>

#define NS   32768
#define NA   2048
#define ASZ  1024
#define KSP  64
#define NB   4
#define NEG_INF (-3.4e38f)
#define CAND_MAX 65536
#define NTILES   4096          // 128x128 tiles per batch: 16 atom-blocks x 256 time-blocks
#define EPS_TOTAL 1.0f         // >= 2*eps for bf16 tile-max error

#define SIG_PAD  512
#define SIG_LEN  33792

typedef unsigned long long ull;

// ---------------- static scratch (~6.5 MB) ----------------
__device__ __align__(16) __nv_bfloat16 g_atoms_bf[(size_t)NA * ASZ];   // 4 MB
__device__ __align__(16) __nv_bfloat16 g_sig8[NB][8][SIG_LEN];         // 2.1 MB
__device__ float    g_tilemax[NB * NTILES];
__device__ float    g_thresh[NB];
__device__ unsigned g_work[NB][NTILES];
__device__ unsigned g_work_cnt[NB];
__device__ float    g_cand_val[NB][CAND_MAX];
__device__ unsigned g_cand_idx[NB][CAND_MAX];
__device__ unsigned g_cand_cnt[NB];
__device__ float    g_topv[NB * KSP];
__device__ unsigned g_topi[NB * KSP];

__device__ __forceinline__ uint32_t smem_u32(const void* p) {
    uint32_t a;
    asm("{ .reg .u64 t; cvta.to.shared.u64 t, %1; cvt.u32.u64 %0, t; }" : "=r"(a) : "l"(p));
    return a;
}
#define CP_ASYNC16(dst, src) \
    asm volatile("cp.async.cg.shared.global [%0], [%1], 16;" :: "r"(dst), "l"(src))
#define CP_COMMIT() asm volatile("cp.async.commit_group;" ::: "memory")
#define CP_WAIT0()  asm volatile("cp.async.wait_group 0;" ::: "memory")

// ---------------- init / prepass ----------------
__global__ void init_kernel() {
    int i = blockIdx.x * blockDim.x + threadIdx.x;
    if (i < NB) { g_cand_cnt[i] = 0u; g_work_cnt[i] = 0u; }
}
__global__ void conv_atoms_kernel(const float* __restrict__ atoms) {
    size_t i = (size_t)blockIdx.x * blockDim.x + threadIdx.x;
    if (i < (size_t)NA * ASZ) g_atoms_bf[i] = __float2bfloat16_rn(atoms[i]);
}
__global__ void build_sig_kernel(const float* __restrict__ orig) {
    size_t i = (size_t)blockIdx.x * blockDim.x + threadIdx.x;
    if (i >= (size_t)NB * 8 * SIG_LEN) return;
    int j = (int)(i % SIG_LEN);
    int c = (int)((i / SIG_LEN) % 8);
    int b = (int)(i / ((size_t)8 * SIG_LEN));
    int s = j - SIG_PAD + c;
    g_sig8[b][c][j] = (s >= 0 && s < NS) ? __float2bfloat16_rn(orig[(size_t)b * NS + s])
                                         : __float2bfloat16_rn(0.f);
}

// ---------------- pass 1: bf16 mma.sync correlation, tile-max only ----------------
// EXACT R6 structure (2,930 us pass): CTA 128 atoms x 128 times, 256 threads, 8 warps
// 4(m)x2(n), warp m32 x n64, K chunks of 32, DOUBLE buffer, two __syncthreads per chunk,
// 2 CTAs/SM. ONLY delta vs R6: fills use cp.async.cg instead of LDG+STS.
//
// smem per buffer (16 KB), R6-validated fragment-packed layout:
//   A 8 KB: [m16b(8)][kb(2)][slot(32)][16B], slot=(r&15)|(h<<4)
//   B 8 KB: [kb(2)][n8b(16)][slot(16)][16B], slot=(t&7)|(h<<3)
__global__ __launch_bounds__(256, 2)
void corr_tc_kernel() {
    __shared__ __align__(128) unsigned char sA[2][8192];
    __shared__ __align__(128) unsigned char sB[2][8192];
    __shared__ float s_wmax[8];

    const int b  = blockIdx.z;
    const int a0 = blockIdx.y << 7;
    const int t0 = blockIdx.x << 7;
    const int tid = threadIdx.x;
    const int w = tid >> 5, lane = tid & 31;
    const int wm = w & 3, wn = w >> 2;

    const uint32_t sA0 = smem_u32(sA[0]), sA1 = smem_u32(sA[1]);
    const uint32_t sB0 = smem_u32(sB[0]), sB1 = smem_u32(sB[1]);

    float acc[2][8][4];
#pragma unroll
    for (int mi = 0; mi < 2; mi++)
#pragma unroll
        for (int ni = 0; ni < 8; ni++)
#pragma unroll
            for (int r = 0; r < 4; r++) acc[mi][ni][r] = 0.f;

    // async fill of one 32-K chunk into buffer `buf` (R6 item mapping, cp.async transport)
    auto fill = [&](int ck, int buf) {
        const int kk = ck << 5;
        const uint32_t aBase = buf ? sA1 : sA0;
        const uint32_t bBase = buf ? sB1 : sB0;
#pragma unroll
        for (int q = 0; q < 2; q++) {
            int i = tid + (q << 8);
            {   // A: atom row r, 8-elem k-group c8
                int r = i >> 2, c8 = i & 3;
                int m16b = r >> 4, kb = c8 >> 1, h = c8 & 1;
                int slot = (r & 15) | (h << 4);
                uint32_t off = (uint32_t)(((((m16b << 1) | kb) << 5) | slot) << 4);
                CP_ASYNC16(aBase + off,
                           (const void*)(g_atoms_bf + (size_t)(a0 + r) * ASZ + kk + (c8 << 3)));
            }
            {   // B: time row t, 8-elem k-group c8
                int t = i >> 2, c8 = i & 3;
                int n8b = t >> 3, kb = c8 >> 1, h = c8 & 1;
                int slot = (t & 7) | (h << 3);
                int c = t & 7;
                uint32_t off = (uint32_t)(((((kb << 4) | n8b) << 4) | slot) << 4);
                CP_ASYNC16(bBase + off,
                           (const void*)(&g_sig8[b][c][t0 + t + kk + (c8 << 3) - c]));
            }
        }
    };

    fill(0, 0); CP_COMMIT();

    for (int ck = 0; ck < 32; ck++) {
        const int p = ck & 1;
        // only fill(ck) is in flight here; drain it, then make visible to all warps
        CP_WAIT0();
        __syncthreads();
        // prefetch next chunk into the other buffer; lands during compute(ck)
        if (ck + 1 < 32) { fill(ck + 1, p ^ 1); CP_COMMIT(); }

        const uint32_t sAp = p ? sA1 : sA0;
        const uint32_t sBp = p ? sB1 : sB0;
#pragma unroll
        for (int kb = 0; kb < 2; kb++) {
            uint32_t a[2][4];
#pragma unroll
            for (int mi = 0; mi < 2; mi++) {
                uint32_t addr = sAp + (uint32_t)((((((wm << 1) | mi) << 1) | kb) << 9) | (lane << 4));
                asm volatile("ldmatrix.sync.aligned.m8n8.x4.shared.b16 {%0,%1,%2,%3}, [%4];"
                    : "=r"(a[mi][0]), "=r"(a[mi][1]), "=r"(a[mi][2]), "=r"(a[mi][3]) : "r"(addr));
            }
#pragma unroll
            for (int jj = 0; jj < 4; jj++) {
                uint32_t bf[2][2];
                uint32_t addr = sBp + (uint32_t)((((kb << 4) | ((wn << 3) + (jj << 1))) << 8) | (lane << 4));
                asm volatile("ldmatrix.sync.aligned.m8n8.x4.shared.b16 {%0,%1,%2,%3}, [%4];"
                    : "=r"(bf[0][0]), "=r"(bf[0][1]), "=r"(bf[1][0]), "=r"(bf[1][1]) : "r"(addr));
#pragma unroll
                for (int mi = 0; mi < 2; mi++)
#pragma unroll
                    for (int nn = 0; nn < 2; nn++)
                        asm volatile(
                            "mma.sync.aligned.m16n8k16.row.col.f32.bf16.bf16.f32 "
                            "{%0,%1,%2,%3}, {%4,%5,%6,%7}, {%8,%9}, {%0,%1,%2,%3};"
                            : "+f"(acc[mi][(jj << 1) + nn][0]), "+f"(acc[mi][(jj << 1) + nn][1]),
                              "+f"(acc[mi][(jj << 1) + nn][2]), "+f"(acc[mi][(jj << 1) + nn][3])
                            : "r"(a[mi][0]), "r"(a[mi][1]), "r"(a[mi][2]), "r"(a[mi][3]),
                              "r"(bf[nn][0]), "r"(bf[nn][1]));
            }
        }
        __syncthreads();   // compute(ck) done before fill(ck+2) can overwrite buffer p
    }

    // epilogue: per-thread max over 64 accs -> warp -> CTA -> g_tilemax
    float m = NEG_INF;
#pragma unroll
    for (int mi = 0; mi < 2; mi++)
#pragma unroll
        for (int ni = 0; ni < 8; ni++)
#pragma unroll
            for (int r = 0; r < 4; r++) m = fmaxf(m, acc[mi][ni][r]);
#pragma unroll
    for (int o = 16; o > 0; o >>= 1) m = fmaxf(m, __shfl_xor_sync(0xffffffffu, m, o));
    if (lane == 0) s_wmax[w] = m;
    __syncthreads();
    if (tid == 0) {
        float mm = s_wmax[0];
#pragma unroll
        for (int i = 1; i < 8; i++) mm = fmaxf(mm, s_wmax[i]);
        g_tilemax[b * NTILES + blockIdx.y * 256 + blockIdx.x] = mm;
    }
}

// ---------------- threshold: (64th-largest approx tile max) - EPS ----------------
__global__ void thresh_kernel() {
    __shared__ float sv[NTILES];
    __shared__ float rv[256];
    __shared__ int   ri[256];
    const int b = blockIdx.x, tid = threadIdx.x;
    for (int i = tid; i < NTILES; i += 256) sv[i] = g_tilemax[b * NTILES + i];
    __syncthreads();
    for (int it = 0; it < KSP; it++) {
        float best = NEG_INF; int bi = 0;
        for (int i = tid; i < NTILES; i += 256)
            if (sv[i] > best) { best = sv[i]; bi = i; }
        rv[tid] = best; ri[tid] = bi;
        __syncthreads();
        for (int s = 128; s > 0; s >>= 1) {
            if (tid < s && rv[tid + s] > rv[tid]) { rv[tid] = rv[tid + s]; ri[tid] = ri[tid + s]; }
            __syncthreads();
        }
        if (tid == 0) {
            if (it == KSP - 1) g_thresh[b] = rv[0] - EPS_TOTAL;
            sv[ri[0]] = NEG_INF;
        }
        __syncthreads();
    }
}

// ---------------- worklist: tiles whose approx max clears the threshold ----------------
__global__ void worklist_kernel() {
    const int b = blockIdx.x;
    const float tau = g_thresh[b];
    for (int i = threadIdx.x; i < NTILES; i += blockDim.x) {
        if (g_tilemax[b * NTILES + i] >= tau) {
            unsigned p = atomicAdd(&g_work_cnt[b], 1u);
            g_work[b][p] = (unsigned)i;
        }
    }
}

// ---------------- exact fp32 tile GEMM (validated R3 core, f32x2 packed) ----------------
__device__ __forceinline__ float f32x2_lo(ull v) { return __uint_as_float((unsigned)(v & 0xffffffffull)); }
__device__ __forceinline__ float f32x2_hi(ull v) { return __uint_as_float((unsigned)(v >> 32)); }

__device__ __forceinline__ void tile_gemm(
    const float* __restrict__ ob, const float* __restrict__ atoms,
    int a0, int t0, int tid, ull acc2[4][8],
    float (*As)[132], float* Bs)
{
    const int tx = tid & 15, ty = tid >> 4;
    const int kload = tid & 15, sload = tid >> 4;
#pragma unroll
    for (int i2 = 0; i2 < 4; i2++)
#pragma unroll
        for (int j = 0; j < 8; j++) acc2[i2][j] = 0ull;

    for (int kk = 0; kk < ASZ; kk += 16) {
#pragma unroll
        for (int i = 0; i < 8; i++) {
            int a = (i << 4) + sload;
            As[kload][a] = atoms[(size_t)(a0 + a) * ASZ + kk + kload];
        }
        if (tid < 160) {
            int src = t0 + kk - 512 + tid;
            Bs[tid] = (src >= 0 && src < NS) ? ob[src] : 0.f;
        }
        __syncthreads();

        unsigned br[24];
#pragma unroll
        for (int q = 0; q < 6; q++) {
            float4 v = *(const float4*)&Bs[(tx << 3) + (q << 2)];
            br[q * 4 + 0] = __float_as_uint(v.x); br[q * 4 + 1] = __float_as_uint(v.y);
            br[q * 4 + 2] = __float_as_uint(v.z); br[q * 4 + 3] = __float_as_uint(v.w);
        }
#pragma unroll
        for (int k = 0; k < 16; k++) {
            ull ar2[4];
#pragma unroll
            for (int i2 = 0; i2 < 4; i2++)
                ar2[i2] = *(const ull*)&As[k][(ty << 3) + (i2 << 1)];
#pragma unroll
            for (int j = 0; j < 8; j++) {
                ull bb;
                asm("mov.b64 %0, {%1, %1};" : "=l"(bb) : "r"(br[k + j]));
#pragma unroll
                for (int i2 = 0; i2 < 4; i2++)
                    asm("fma.rn.f32x2 %0, %1, %2, %0;"
                        : "+l"(acc2[i2][j]) : "l"(ar2[i2]), "l"(bb));
            }
        }
        __syncthreads();
    }
}

// ---------------- pass 2: exact recompute of hot tiles, compact candidates ----------------
__global__ __launch_bounds__(256, 2)
void recompute_kernel(const float* __restrict__ orig, const float* __restrict__ atoms) {
    __shared__ float As[16][132];
    __shared__ float Bs[160];
    const int b = blockIdx.y;
    const float tau = g_thresh[b];
    const unsigned cnt = g_work_cnt[b];
    const int tid = threadIdx.x;
    const int tx = tid & 15, ty = tid >> 4;

    for (unsigned w = blockIdx.x; w < cnt; w += gridDim.x) {
        unsigned tile = g_work[b][w];
        int a0 = (int)(tile >> 8) << 7;          // tile = atom_blk*256 + time_blk
        int t0 = (int)(tile & 255u) << 7;
        ull acc2[4][8];
        tile_gemm(orig + (size_t)b * NS, atoms, a0, t0, tid, acc2, As, Bs);

#pragma unroll
        for (int i2 = 0; i2 < 4; i2++) {
#pragma unroll
            for (int j = 0; j < 8; j++) {
                float vlo = f32x2_lo(acc2[i2][j]);
                float vhi = f32x2_hi(acc2[i2][j]);
                int abase = a0 + (ty << 3) + (i2 << 1);
                int t = t0 + (tx << 3) + j;
                if (vlo >= tau) {
                    unsigned pos = atomicAdd(&g_cand_cnt[b], 1u);
                    if (pos < CAND_MAX) {
                        g_cand_val[b][pos] = vlo;
                        g_cand_idx[b][pos] = (unsigned)abase * (unsigned)NS + (unsigned)t;
                    }
                }
                if (vhi >= tau) {
                    unsigned pos = atomicAdd(&g_cand_cnt[b], 1u);
                    if (pos < CAND_MAX) {
                        g_cand_val[b][pos] = vhi;
                        g_cand_idx[b][pos] = (unsigned)(abase + 1) * (unsigned)NS + (unsigned)t;
                    }
                }
            }
        }
        __syncthreads();
    }
}

// ---------------- exact top-64 among candidates ----------------
__global__ void select_kernel() {
    __shared__ float rv[256];
    __shared__ int   ri[256];
    const int b = blockIdx.x, tid = threadIdx.x;
    unsigned n = g_cand_cnt[b];
    if (n > CAND_MAX) n = CAND_MAX;
    for (int it = 0; it < KSP; it++) {
        float best = NEG_INF; int bi = 0;
        for (unsigned i = tid; i < n; i += 256) {
            float v = g_cand_val[b][i];
            if (v > best) { best = v; bi = (int)i; }
        }
        rv[tid] = best; ri[tid] = bi;
        __syncthreads();
        for (int s = 128; s > 0; s >>= 1) {
            if (tid < s && rv[tid + s] > rv[tid]) { rv[tid] = rv[tid + s]; ri[tid] = ri[tid + s]; }
            __syncthreads();
        }
        if (tid == 0) {
            g_topv[b * KSP + it] = rv[0];
            g_topi[b * KSP + it] = g_cand_idx[b][ri[0]];
            g_cand_val[b][ri[0]] = NEG_INF;
        }
        __syncthreads();
    }
}

// ---------------- reconstruction: deterministic gather ----------------
__global__ void output_kernel(const float* __restrict__ atoms, float* __restrict__ out) {
    __shared__ float sv[KSP];
    __shared__ int   sa[KSP];
    __shared__ int   st[KSP];
    const int b = blockIdx.y, tid = threadIdx.x;
    if (tid < KSP) {
        sv[tid] = g_topv[b * KSP + tid];
        unsigned idx = g_topi[b * KSP + tid];
        sa[tid] = (int)(idx / (unsigned)NS);
        st[tid] = (int)(idx % (unsigned)NS);
    }
    __syncthreads();
    const int p = blockIdx.x * blockDim.x + tid;
    float acc = 0.f;
#pragma unroll 8
    for (int j = 0; j < KSP; j++) {
        int o = p - st[j];
        if ((unsigned)o < (unsigned)ASZ) acc += atoms[(size_t)sa[j] * ASZ + o] * sv[j];
    }
    out[(size_t)b * NS + p] = acc;
}

// ---------------- launch ----------------
extern "C" void kernel_launch(void* const* d_in, const int* in_sizes, int n_in,
                              void* d_out, int out_size) {
    const float* orig  = (const float*)d_in[0];
    const float* atoms = (const float*)d_in[1];
    if (n_in >= 2 && in_sizes[0] == NA * ASZ) {   // defensive operand-order check
        const float* t = orig; orig = atoms; atoms = t;
    }
    float* out = (float*)d_out;

    init_kernel<<<1, 32>>>();
    conv_atoms_kernel<<<(NA * ASZ + 255) / 256, 256>>>(atoms);
    build_sig_kernel<<<(NB * 8 * SIG_LEN + 255) / 256, 256>>>(orig);
    corr_tc_kernel<<<dim3(256, 16, NB), 256>>>();
    thresh_kernel<<<NB, 256>>>();
    worklist_kernel<<<NB, 256>>>();
    recompute_kernel<<<dim3(256, NB), 256>>>(orig, atoms);
    select_kernel<<<NB, 256>>>();
    output_kernel<<<dim3(NS / 256, NB), 256>>>(atoms, out);
}

// round 15
// speedup vs baseline: 1.1914x; 1.0150x over previous
#include <cuda_runtime.h>
#include <cuda_bf16.h>
#include <cstdint>

#define NS   32768
#define NA   2048
#define ASZ  1024
#define KSP  64
#define NB   4
#define NEG_INF (-3.4e38f)
#define CAND_MAX 65536
#define NTILES   4096          // 128x128 tiles per batch: 16 atom-blocks x 256 time-blocks
#define EPS_TOTAL 1.0f         // >= 2*eps for bf16 tile-max error

#define SIG_PAD  512
#define SIG_LEN  33792

typedef unsigned long long ull;

// ---------------- static scratch (~6.5 MB) ----------------
__device__ __align__(16) __nv_bfloat16 g_atoms_bf[(size_t)NA * ASZ];   // 4 MB
__device__ __align__(16) __nv_bfloat16 g_sig8[NB][8][SIG_LEN];         // 2.1 MB
__device__ float    g_tilemax[NB * NTILES];
__device__ float    g_thresh[NB];
__device__ unsigned g_work[NB][NTILES];
__device__ unsigned g_work_cnt[NB];
__device__ float    g_cand_val[NB][CAND_MAX];
__device__ unsigned g_cand_idx[NB][CAND_MAX];
__device__ unsigned g_cand_cnt[NB];
__device__ float    g_topv[NB * KSP];
__device__ unsigned g_topi[NB * KSP];

__device__ __forceinline__ uint32_t smem_u32(const void* p) {
    uint32_t a;
    asm("{ .reg .u64 t; cvta.to.shared.u64 t, %1; cvt.u32.u64 %0, t; }" : "=r"(a) : "l"(p));
    return a;
}
#define CP_ASYNC16(dst, src) \
    asm volatile("cp.async.cg.shared.global [%0], [%1], 16;" :: "r"(dst), "l"(src))
#define CP_COMMIT() asm volatile("cp.async.commit_group;" ::: "memory")
#define CP_WAIT0()  asm volatile("cp.async.wait_group 0;" ::: "memory")

// ---------------- init / prepass ----------------
__global__ void init_kernel() {
    int i = blockIdx.x * blockDim.x + threadIdx.x;
    if (i < NB) { g_cand_cnt[i] = 0u; g_work_cnt[i] = 0u; }
}
__global__ void conv_atoms_kernel(const float* __restrict__ atoms) {
    size_t i = (size_t)blockIdx.x * blockDim.x + threadIdx.x;
    if (i < (size_t)NA * ASZ) g_atoms_bf[i] = __float2bfloat16_rn(atoms[i]);
}
__global__ void build_sig_kernel(const float* __restrict__ orig) {
    size_t i = (size_t)blockIdx.x * blockDim.x + threadIdx.x;
    if (i >= (size_t)NB * 8 * SIG_LEN) return;
    int j = (int)(i % SIG_LEN);
    int c = (int)((i / SIG_LEN) % 8);
    int b = (int)(i / ((size_t)8 * SIG_LEN));
    int s = j - SIG_PAD + c;
    g_sig8[b][c][j] = (s >= 0 && s < NS) ? __float2bfloat16_rn(orig[(size_t)b * NS + s])
                                         : __float2bfloat16_rn(0.f);
}

// ---------------- pass 1: bf16 mma.sync correlation, tile-max only ----------------
// EXACT R12 structure (3,070 us pass) with ONE change: the bottom __syncthreads in the
// main loop is removed. Safety: at iter ck+1, the top CP_WAIT0+__syncthreads is reached
// by a warp only after it finished compute(ck) on buffer p, and all later fills are
// issued after that barrier -> buffer overwrite is ordered after all reads.
//
// CTA 128 atoms x 128 times, 256 threads, 8 warps 4(m)x2(n), warp m32 x n64,
// 32 chunks of K=32, double buffer, cp.async.cg fills, 2 CTAs/SM.
// smem per buffer (16 KB), R6-validated fragment-packed layout:
//   A 8 KB: [m16b(8)][kb(2)][slot(32)][16B], slot = (r&15)|(h<<4)
//   B 8 KB: [kb(2)][n8b(16)][slot(16)][16B], slot = (t&7)|(h<<3)
__global__ __launch_bounds__(256, 2)
void corr_tc_kernel() {
    __shared__ __align__(128) unsigned char sA[2][8192];
    __shared__ __align__(128) unsigned char sB[2][8192];
    __shared__ float s_wmax[8];

    const int b  = blockIdx.z;
    const int a0 = blockIdx.y << 7;
    const int t0 = blockIdx.x << 7;
    const int tid = threadIdx.x;
    const int w = tid >> 5, lane = tid & 31;
    const int wm = w & 3, wn = w >> 2;

    const uint32_t sA0 = smem_u32(sA[0]), sA1 = smem_u32(sA[1]);
    const uint32_t sB0 = smem_u32(sB[0]), sB1 = smem_u32(sB[1]);

    float acc[2][8][4];
#pragma unroll
    for (int mi = 0; mi < 2; mi++)
#pragma unroll
        for (int ni = 0; ni < 8; ni++)
#pragma unroll
            for (int r = 0; r < 4; r++) acc[mi][ni][r] = 0.f;

    // async fill of one 32-K chunk into buffer `buf` (R6 item mapping, cp.async transport)
    auto fill = [&](int ck, int buf) {
        const int kk = ck << 5;
        const uint32_t aBase = buf ? sA1 : sA0;
        const uint32_t bBase = buf ? sB1 : sB0;
#pragma unroll
        for (int q = 0; q < 2; q++) {
            int i = tid + (q << 8);
            {   // A: atom row r, 8-elem k-group c8
                int r = i >> 2, c8 = i & 3;
                int m16b = r >> 4, kb = c8 >> 1, h = c8 & 1;
                int slot = (r & 15) | (h << 4);
                uint32_t off = (uint32_t)(((((m16b << 1) | kb) << 5) | slot) << 4);
                CP_ASYNC16(aBase + off,
                           (const void*)(g_atoms_bf + (size_t)(a0 + r) * ASZ + kk + (c8 << 3)));
            }
            {   // B: time row t, 8-elem k-group c8
                int t = i >> 2, c8 = i & 3;
                int n8b = t >> 3, kb = c8 >> 1, h = c8 & 1;
                int slot = (t & 7) | (h << 3);
                int c = t & 7;
                uint32_t off = (uint32_t)(((((kb << 4) | n8b) << 4) | slot) << 4);
                CP_ASYNC16(bBase + off,
                           (const void*)(&g_sig8[b][c][t0 + t + kk + (c8 << 3) - c]));
            }
        }
    };

    fill(0, 0); CP_COMMIT();

    for (int ck = 0; ck < 32; ck++) {
        const int p = ck & 1;
        // only fill(ck) is in flight here; drain it, then publish to all warps.
        // This barrier also orders every warp's compute(ck-1) before the fills below.
        CP_WAIT0();
        __syncthreads();
        if (ck + 1 < 32) { fill(ck + 1, p ^ 1); CP_COMMIT(); }

        const uint32_t sAp = p ? sA1 : sA0;
        const uint32_t sBp = p ? sB1 : sB0;
#pragma unroll
        for (int kb = 0; kb < 2; kb++) {
            uint32_t a[2][4];
#pragma unroll
            for (int mi = 0; mi < 2; mi++) {
                uint32_t addr = sAp + (uint32_t)((((((wm << 1) | mi) << 1) | kb) << 9) | (lane << 4));
                asm volatile("ldmatrix.sync.aligned.m8n8.x4.shared.b16 {%0,%1,%2,%3}, [%4];"
                    : "=r"(a[mi][0]), "=r"(a[mi][1]), "=r"(a[mi][2]), "=r"(a[mi][3]) : "r"(addr));
            }
#pragma unroll
            for (int jj = 0; jj < 4; jj++) {
                uint32_t bf[2][2];
                uint32_t addr = sBp + (uint32_t)((((kb << 4) | ((wn << 3) + (jj << 1))) << 8) | (lane << 4));
                asm volatile("ldmatrix.sync.aligned.m8n8.x4.shared.b16 {%0,%1,%2,%3}, [%4];"
                    : "=r"(bf[0][0]), "=r"(bf[0][1]), "=r"(bf[1][0]), "=r"(bf[1][1]) : "r"(addr));
#pragma unroll
                for (int mi = 0; mi < 2; mi++)
#pragma unroll
                    for (int nn = 0; nn < 2; nn++)
                        asm volatile(
                            "mma.sync.aligned.m16n8k16.row.col.f32.bf16.bf16.f32 "
                            "{%0,%1,%2,%3}, {%4,%5,%6,%7}, {%8,%9}, {%0,%1,%2,%3};"
                            : "+f"(acc[mi][(jj << 1) + nn][0]), "+f"(acc[mi][(jj << 1) + nn][1]),
                              "+f"(acc[mi][(jj << 1) + nn][2]), "+f"(acc[mi][(jj << 1) + nn][3])
                            : "r"(a[mi][0]), "r"(a[mi][1]), "r"(a[mi][2]), "r"(a[mi][3]),
                              "r"(bf[nn][0]), "r"(bf[nn][1]));
            }
        }
        // (bottom __syncthreads removed -- ordering provided by next iteration's top barrier)
    }

    // epilogue: per-thread max over 64 accs -> warp -> CTA -> g_tilemax
    float m = NEG_INF;
#pragma unroll
    for (int mi = 0; mi < 2; mi++)
#pragma unroll
        for (int ni = 0; ni < 8; ni++)
#pragma unroll
            for (int r = 0; r < 4; r++) m = fmaxf(m, acc[mi][ni][r]);
#pragma unroll
    for (int o = 16; o > 0; o >>= 1) m = fmaxf(m, __shfl_xor_sync(0xffffffffu, m, o));
    if (lane == 0) s_wmax[w] = m;
    __syncthreads();
    if (tid == 0) {
        float mm = s_wmax[0];
#pragma unroll
        for (int i = 1; i < 8; i++) mm = fmaxf(mm, s_wmax[i]);
        g_tilemax[b * NTILES + blockIdx.y * 256 + blockIdx.x] = mm;
    }
}

// ---------------- threshold: (64th-largest approx tile max) - EPS ----------------
__global__ void thresh_kernel() {
    __shared__ float sv[NTILES];
    __shared__ float rv[256];
    __shared__ int   ri[256];
    const int b = blockIdx.x, tid = threadIdx.x;
    for (int i = tid; i < NTILES; i += 256) sv[i] = g_tilemax[b * NTILES + i];
    __syncthreads();
    for (int it = 0; it < KSP; it++) {
        float best = NEG_INF; int bi = 0;
        for (int i = tid; i < NTILES; i += 256)
            if (sv[i] > best) { best = sv[i]; bi = i; }
        rv[tid] = best; ri[tid] = bi;
        __syncthreads();
        for (int s = 128; s > 0; s >>= 1) {
            if (tid < s && rv[tid + s] > rv[tid]) { rv[tid] = rv[tid + s]; ri[tid] = ri[tid + s]; }
            __syncthreads();
        }
        if (tid == 0) {
            if (it == KSP - 1) g_thresh[b] = rv[0] - EPS_TOTAL;
            sv[ri[0]] = NEG_INF;
        }
        __syncthreads();
    }
}

// ---------------- worklist: tiles whose approx max clears the threshold ----------------
__global__ void worklist_kernel() {
    const int b = blockIdx.x;
    const float tau = g_thresh[b];
    for (int i = threadIdx.x; i < NTILES; i += blockDim.x) {
        if (g_tilemax[b * NTILES + i] >= tau) {
            unsigned p = atomicAdd(&g_work_cnt[b], 1u);
            g_work[b][p] = (unsigned)i;
        }
    }
}

// ---------------- exact fp32 tile GEMM (validated R3 core, f32x2 packed) ----------------
__device__ __forceinline__ float f32x2_lo(ull v) { return __uint_as_float((unsigned)(v & 0xffffffffull)); }
__device__ __forceinline__ float f32x2_hi(ull v) { return __uint_as_float((unsigned)(v >> 32)); }

__device__ __forceinline__ void tile_gemm(
    const float* __restrict__ ob, const float* __restrict__ atoms,
    int a0, int t0, int tid, ull acc2[4][8],
    float (*As)[132], float* Bs)
{
    const int tx = tid & 15, ty = tid >> 4;
    const int kload = tid & 15, sload = tid >> 4;
#pragma unroll
    for (int i2 = 0; i2 < 4; i2++)
#pragma unroll
        for (int j = 0; j < 8; j++) acc2[i2][j] = 0ull;

    for (int kk = 0; kk < ASZ; kk += 16) {
#pragma unroll
        for (int i = 0; i < 8; i++) {
            int a = (i << 4) + sload;
            As[kload][a] = atoms[(size_t)(a0 + a) * ASZ + kk + kload];
        }
        if (tid < 160) {
            int src = t0 + kk - 512 + tid;
            Bs[tid] = (src >= 0 && src < NS) ? ob[src] : 0.f;
        }
        __syncthreads();

        unsigned br[24];
#pragma unroll
        for (int q = 0; q < 6; q++) {
            float4 v = *(const float4*)&Bs[(tx << 3) + (q << 2)];
            br[q * 4 + 0] = __float_as_uint(v.x); br[q * 4 + 1] = __float_as_uint(v.y);
            br[q * 4 + 2] = __float_as_uint(v.z); br[q * 4 + 3] = __float_as_uint(v.w);
        }
#pragma unroll
        for (int k = 0; k < 16; k++) {
            ull ar2[4];
#pragma unroll
            for (int i2 = 0; i2 < 4; i2++)
                ar2[i2] = *(const ull*)&As[k][(ty << 3) + (i2 << 1)];
#pragma unroll
            for (int j = 0; j < 8; j++) {
                ull bb;
                asm("mov.b64 %0, {%1, %1};" : "=l"(bb) : "r"(br[k + j]));
#pragma unroll
                for (int i2 = 0; i2 < 4; i2++)
                    asm("fma.rn.f32x2 %0, %1, %2, %0;"
                        : "+l"(acc2[i2][j]) : "l"(ar2[i2]), "l"(bb));
            }
        }
        __syncthreads();
    }
}

// ---------------- pass 2: exact recompute of hot tiles, compact candidates ----------------
__global__ __launch_bounds__(256, 2)
void recompute_kernel(const float* __restrict__ orig, const float* __restrict__ atoms) {
    __shared__ float As[16][132];
    __shared__ float Bs[160];
    const int b = blockIdx.y;
    const float tau = g_thresh[b];
    const unsigned cnt = g_work_cnt[b];
    const int tid = threadIdx.x;
    const int tx = tid & 15, ty = tid >> 4;

    for (unsigned w = blockIdx.x; w < cnt; w += gridDim.x) {
        unsigned tile = g_work[b][w];
        int a0 = (int)(tile >> 8) << 7;          // tile = atom_blk*256 + time_blk
        int t0 = (int)(tile & 255u) << 7;
        ull acc2[4][8];
        tile_gemm(orig + (size_t)b * NS, atoms, a0, t0, tid, acc2, As, Bs);

#pragma unroll
        for (int i2 = 0; i2 < 4; i2++) {
#pragma unroll
            for (int j = 0; j < 8; j++) {
                float vlo = f32x2_lo(acc2[i2][j]);
                float vhi = f32x2_hi(acc2[i2][j]);
                int abase = a0 + (ty << 3) + (i2 << 1);
                int t = t0 + (tx << 3) + j;
                if (vlo >= tau) {
                    unsigned pos = atomicAdd(&g_cand_cnt[b], 1u);
                    if (pos < CAND_MAX) {
                        g_cand_val[b][pos] = vlo;
                        g_cand_idx[b][pos] = (unsigned)abase * (unsigned)NS + (unsigned)t;
                    }
                }
                if (vhi >= tau) {
                    unsigned pos = atomicAdd(&g_cand_cnt[b], 1u);
                    if (pos < CAND_MAX) {
                        g_cand_val[b][pos] = vhi;
                        g_cand_idx[b][pos] = (unsigned)(abase + 1) * (unsigned)NS + (unsigned)t;
                    }
                }
            }
        }
        __syncthreads();
    }
}

// ---------------- exact top-64 among candidates ----------------
__global__ void select_kernel() {
    __shared__ float rv[256];
    __shared__ int   ri[256];
    const int b = blockIdx.x, tid = threadIdx.x;
    unsigned n = g_cand_cnt[b];
    if (n > CAND_MAX) n = CAND_MAX;
    for (int it = 0; it < KSP; it++) {
        float best = NEG_INF; int bi = 0;
        for (unsigned i = tid; i < n; i += 256) {
            float v = g_cand_val[b][i];
            if (v > best) { best = v; bi = (int)i; }
        }
        rv[tid] = best; ri[tid] = bi;
        __syncthreads();
        for (int s = 128; s > 0; s >>= 1) {
            if (tid < s && rv[tid + s] > rv[tid]) { rv[tid] = rv[tid + s]; ri[tid] = ri[tid + s]; }
            __syncthreads();
        }
        if (tid == 0) {
            g_topv[b * KSP + it] = rv[0];
            g_topi[b * KSP + it] = g_cand_idx[b][ri[0]];
            g_cand_val[b][ri[0]] = NEG_INF;
        }
        __syncthreads();
    }
}

// ---------------- reconstruction: deterministic gather ----------------
__global__ void output_kernel(const float* __restrict__ atoms, float* __restrict__ out) {
    __shared__ float sv[KSP];
    __shared__ int   sa[KSP];
    __shared__ int   st[KSP];
    const int b = blockIdx.y, tid = threadIdx.x;
    if (tid < KSP) {
        sv[tid] = g_topv[b * KSP + tid];
        unsigned idx = g_topi[b * KSP + tid];
        sa[tid] = (int)(idx / (unsigned)NS);
        st[tid] = (int)(idx % (unsigned)NS);
    }
    __syncthreads();
    const int p = blockIdx.x * blockDim.x + tid;
    float acc = 0.f;
#pragma unroll 8
    for (int j = 0; j < KSP; j++) {
        int o = p - st[j];
        if ((unsigned)o < (unsigned)ASZ) acc += atoms[(size_t)sa[j] * ASZ + o] * sv[j];
    }
    out[(size_t)b * NS + p] = acc;
}

// ---------------- launch ----------------
extern "C" void kernel_launch(void* const* d_in, const int* in_sizes, int n_in,
                              void* d_out, int out_size) {
    const float* orig  = (const float*)d_in[0];
    const float* atoms = (const float*)d_in[1];
    if (n_in >= 2 && in_sizes[0] == NA * ASZ) {   // defensive operand-order check
        const float* t = orig; orig = atoms; atoms = t;
    }
    float* out = (float*)d_out;

    init_kernel<<<1, 32>>>();
    conv_atoms_kernel<<<(NA * ASZ + 255) / 256, 256>>>(atoms);
    build_sig_kernel<<<(NB * 8 * SIG_LEN + 255) / 256, 256>>>(orig);
    corr_tc_kernel<<<dim3(256, 16, NB), 256>>>();
    thresh_kernel<<<NB, 256>>>();
    worklist_kernel<<<NB, 256>>>();
    recompute_kernel<<<dim3(256, NB), 256>>>(orig, atoms);
    select_kernel<<<NB, 256>>>();
    output_kernel<<<dim3(NS / 256, NB), 256>>>(atoms, out);
}

// round 16
// speedup vs baseline: 2.2196x; 1.8631x over previous
#include <cuda_runtime.h>
#include <cuda_bf16.h>
#include <cstdint>

#define NS   32768
#define NA   2048
#define ASZ  1024
#define KSP  64
#define NB   4
#define NEG_INF (-3.4e38f)
#define CAND_MAX 65536
#define NTILES   4096          // 128x128 tiles per batch: 16 atom-blocks x 256 time-blocks
#define EPS_TOTAL 1.5f         // >= 2*eps for int8 tile-max error (~6.7 sigma)

#define SIG_PAD  512
#define SIG_LEN  33792
#define ATOM_SCALE 127.0f
#define SIG_SCALE  25.0f
#define CORR_INV   (1.0f / (ATOM_SCALE * SIG_SCALE))

typedef unsigned long long ull;

// ---------------- static scratch (~4.5 MB) ----------------
__device__ __align__(16) signed char g_atoms_i8[(size_t)NA * ASZ];     // 2 MB
__device__ __align__(16) signed char g_sig16[NB][16][SIG_LEN];         // 2.16 MB
__device__ float    g_tilemax[NB * NTILES];
__device__ float    g_thresh[NB];
__device__ unsigned g_work[NB][NTILES];
__device__ unsigned g_work_cnt[NB];
__device__ float    g_cand_val[NB][CAND_MAX];
__device__ unsigned g_cand_idx[NB][CAND_MAX];
__device__ unsigned g_cand_cnt[NB];
__device__ float    g_topv[NB * KSP];
__device__ unsigned g_topi[NB * KSP];

__device__ __forceinline__ uint32_t smem_u32(const void* p) {
    uint32_t a;
    asm("{ .reg .u64 t; cvta.to.shared.u64 t, %1; cvt.u32.u64 %0, t; }" : "=r"(a) : "l"(p));
    return a;
}
#define CP_ASYNC16(dst, src) \
    asm volatile("cp.async.cg.shared.global [%0], [%1], 16;" :: "r"(dst), "l"(src))
#define CP_COMMIT() asm volatile("cp.async.commit_group;" ::: "memory")
#define CP_WAIT0()  asm volatile("cp.async.wait_group 0;" ::: "memory")

// ---------------- init / prepass ----------------
__global__ void init_kernel() {
    int i = blockIdx.x * blockDim.x + threadIdx.x;
    if (i < NB) { g_cand_cnt[i] = 0u; g_work_cnt[i] = 0u; }
}
__global__ void conv_atoms_kernel(const float* __restrict__ atoms) {
    size_t i = (size_t)blockIdx.x * blockDim.x + threadIdx.x;
    if (i < (size_t)NA * ASZ) {
        int v = __float2int_rn(atoms[i] * ATOM_SCALE);
        v = v < -127 ? -127 : (v > 127 ? 127 : v);
        g_atoms_i8[i] = (signed char)v;
    }
}
__global__ void build_sig_kernel(const float* __restrict__ orig) {
    size_t i = (size_t)blockIdx.x * blockDim.x + threadIdx.x;
    if (i >= (size_t)NB * 16 * SIG_LEN) return;
    int j = (int)(i % SIG_LEN);
    int c = (int)((i / SIG_LEN) & 15);
    int b = (int)(i / ((size_t)16 * SIG_LEN));
    int s = j - SIG_PAD + c;
    int v = 0;
    if (s >= 0 && s < NS) {
        v = __float2int_rn(orig[(size_t)b * NS + s] * SIG_SCALE);
        v = v < -127 ? -127 : (v > 127 ? 127 : v);
    }
    g_sig16[b][c][j] = (signed char)v;
}

// ---------------- pass 1: int8 mma.sync correlation, tile-max only ----------------
// Same byte-level smem layout and addressing as the R15 bf16 kernel; the s8 m16n8k32
// fragment spec maps onto the identical 4-submatrix ldmatrix order. K per chunk = 64
// int8 (64 B/row, same as 32 bf16), so NCHUNK halves to 16 and MMA count halves.
// CTA 128 atoms x 128 times, 256 threads, 8 warps 4(m)x2(n), warp m32 x n64,
// double buffer, cp.async.cg fills, one __syncthreads per chunk, 2 CTAs/SM.
//   A 8 KB: [m16b(8)][kb(2)][slot(32)][16B], slot = (r&15)|(h<<4)   (kb = k32 block, h = 16B half)
//   B 8 KB: [kb(2)][n8b(16)][slot(16)][16B], slot = (t&7)|(h<<3)
#define NCHUNK 16
__global__ __launch_bounds__(256, 2)
void corr_tc_kernel() {
    __shared__ __align__(128) unsigned char sA[2][8192];
    __shared__ __align__(128) unsigned char sB[2][8192];
    __shared__ float s_wmax[8];

    const int b  = blockIdx.z;
    const int a0 = blockIdx.y << 7;
    const int t0 = blockIdx.x << 7;
    const int tid = threadIdx.x;
    const int w = tid >> 5, lane = tid & 31;
    const int wm = w & 3, wn = w >> 2;

    const uint32_t sA0 = smem_u32(sA[0]), sA1 = smem_u32(sA[1]);
    const uint32_t sB0 = smem_u32(sB[0]), sB1 = smem_u32(sB[1]);

    int acc[2][8][4];
#pragma unroll
    for (int mi = 0; mi < 2; mi++)
#pragma unroll
        for (int ni = 0; ni < 8; ni++)
#pragma unroll
            for (int r = 0; r < 4; r++) acc[mi][ni][r] = 0;

    // async fill of one 64-K chunk into buffer `buf` (A: 512 16B items, B: 512; 2+2/thread)
    auto fill = [&](int ck, int buf) {
        const int kk = ck << 6;
        const uint32_t aBase = buf ? sA1 : sA0;
        const uint32_t bBase = buf ? sB1 : sB0;
#pragma unroll
        for (int q = 0; q < 2; q++) {
            int i = tid + (q << 8);
            {   // A: atom row r, 16-byte k-group c8 (0..3)
                int r = i >> 2, c8 = i & 3;
                int m16b = r >> 4, kb = c8 >> 1, h = c8 & 1;
                int slot = (r & 15) | (h << 4);
                uint32_t off = (uint32_t)(((((m16b << 1) | kb) << 5) | slot) << 4);
                CP_ASYNC16(aBase + off,
                           (const void*)(g_atoms_i8 + (size_t)(a0 + r) * ASZ + kk + (c8 << 4)));
            }
            {   // B: time row t, 16-byte k-group c8
                int t = i >> 2, c8 = i & 3;
                int n8b = t >> 3, kb = c8 >> 1, h = c8 & 1;
                int slot = (t & 7) | (h << 3);
                int c = t & 15;                 // replica so src is 16B-aligned
                uint32_t off = (uint32_t)(((((kb << 4) | n8b) << 4) | slot) << 4);
                CP_ASYNC16(bBase + off,
                           (const void*)(&g_sig16[b][c][t0 + t + kk + (c8 << 4) - c]));
            }
        }
    };

    fill(0, 0); CP_COMMIT();

    for (int ck = 0; ck < NCHUNK; ck++) {
        const int p = ck & 1;
        // only fill(ck) is in flight; drain, publish. Barrier also orders all warps'
        // compute(ck-1) before the fills below overwrite the other buffer.
        CP_WAIT0();
        __syncthreads();
        if (ck + 1 < NCHUNK) { fill(ck + 1, p ^ 1); CP_COMMIT(); }

        const uint32_t sAp = p ? sA1 : sA0;
        const uint32_t sBp = p ? sB1 : sB0;
#pragma unroll
        for (int kb = 0; kb < 2; kb++) {
            uint32_t a[2][4];
#pragma unroll
            for (int mi = 0; mi < 2; mi++) {
                uint32_t addr = sAp + (uint32_t)((((((wm << 1) | mi) << 1) | kb) << 9) | (lane << 4));
                asm volatile("ldmatrix.sync.aligned.m8n8.x4.shared.b16 {%0,%1,%2,%3}, [%4];"
                    : "=r"(a[mi][0]), "=r"(a[mi][1]), "=r"(a[mi][2]), "=r"(a[mi][3]) : "r"(addr));
            }
#pragma unroll
            for (int jj = 0; jj < 4; jj++) {
                uint32_t bf[2][2];
                uint32_t addr = sBp + (uint32_t)((((kb << 4) | ((wn << 3) + (jj << 1))) << 8) | (lane << 4));
                asm volatile("ldmatrix.sync.aligned.m8n8.x4.shared.b16 {%0,%1,%2,%3}, [%4];"
                    : "=r"(bf[0][0]), "=r"(bf[0][1]), "=r"(bf[1][0]), "=r"(bf[1][1]) : "r"(addr));
#pragma unroll
                for (int mi = 0; mi < 2; mi++)
#pragma unroll
                    for (int nn = 0; nn < 2; nn++)
                        asm volatile(
                            "mma.sync.aligned.m16n8k32.row.col.s32.s8.s8.s32 "
                            "{%0,%1,%2,%3}, {%4,%5,%6,%7}, {%8,%9}, {%0,%1,%2,%3};"
                            : "+r"(acc[mi][(jj << 1) + nn][0]), "+r"(acc[mi][(jj << 1) + nn][1]),
                              "+r"(acc[mi][(jj << 1) + nn][2]), "+r"(acc[mi][(jj << 1) + nn][3])
                            : "r"(a[mi][0]), "r"(a[mi][1]), "r"(a[mi][2]), "r"(a[mi][3]),
                              "r"(bf[nn][0]), "r"(bf[nn][1]));
            }
        }
    }

    // epilogue: int max over 64 accs (scale is positive, monotonic) -> float tile max
    int im = -2147483647;
#pragma unroll
    for (int mi = 0; mi < 2; mi++)
#pragma unroll
        for (int ni = 0; ni < 8; ni++)
#pragma unroll
            for (int r = 0; r < 4; r++) im = max(im, acc[mi][ni][r]);
    float m = (float)im * CORR_INV;
#pragma unroll
    for (int o = 16; o > 0; o >>= 1) m = fmaxf(m, __shfl_xor_sync(0xffffffffu, m, o));
    if (lane == 0) s_wmax[w] = m;
    __syncthreads();
    if (tid == 0) {
        float mm = s_wmax[0];
#pragma unroll
        for (int i = 1; i < 8; i++) mm = fmaxf(mm, s_wmax[i]);
        g_tilemax[b * NTILES + blockIdx.y * 256 + blockIdx.x] = mm;
    }
}

// ---------------- threshold: (64th-largest approx tile max) - EPS ----------------
__global__ void thresh_kernel() {
    __shared__ float sv[NTILES];
    __shared__ float rv[256];
    __shared__ int   ri[256];
    const int b = blockIdx.x, tid = threadIdx.x;
    for (int i = tid; i < NTILES; i += 256) sv[i] = g_tilemax[b * NTILES + i];
    __syncthreads();
    for (int it = 0; it < KSP; it++) {
        float best = NEG_INF; int bi = 0;
        for (int i = tid; i < NTILES; i += 256)
            if (sv[i] > best) { best = sv[i]; bi = i; }
        rv[tid] = best; ri[tid] = bi;
        __syncthreads();
        for (int s = 128; s > 0; s >>= 1) {
            if (tid < s && rv[tid + s] > rv[tid]) { rv[tid] = rv[tid + s]; ri[tid] = ri[tid + s]; }
            __syncthreads();
        }
        if (tid == 0) {
            if (it == KSP - 1) g_thresh[b] = rv[0] - EPS_TOTAL;
            sv[ri[0]] = NEG_INF;
        }
        __syncthreads();
    }
}

// ---------------- worklist: tiles whose approx max clears the threshold ----------------
__global__ void worklist_kernel() {
    const int b = blockIdx.x;
    const float tau = g_thresh[b];
    for (int i = threadIdx.x; i < NTILES; i += blockDim.x) {
        if (g_tilemax[b * NTILES + i] >= tau) {
            unsigned p = atomicAdd(&g_work_cnt[b], 1u);
            g_work[b][p] = (unsigned)i;
        }
    }
}

// ---------------- exact fp32 tile GEMM (validated R3 core, f32x2 packed) ----------------
__device__ __forceinline__ float f32x2_lo(ull v) { return __uint_as_float((unsigned)(v & 0xffffffffull)); }
__device__ __forceinline__ float f32x2_hi(ull v) { return __uint_as_float((unsigned)(v >> 32)); }

__device__ __forceinline__ void tile_gemm(
    const float* __restrict__ ob, const float* __restrict__ atoms,
    int a0, int t0, int tid, ull acc2[4][8],
    float (*As)[132], float* Bs)
{
    const int tx = tid & 15, ty = tid >> 4;
    const int kload = tid & 15, sload = tid >> 4;
#pragma unroll
    for (int i2 = 0; i2 < 4; i2++)
#pragma unroll
        for (int j = 0; j < 8; j++) acc2[i2][j] = 0ull;

    for (int kk = 0; kk < ASZ; kk += 16) {
#pragma unroll
        for (int i = 0; i < 8; i++) {
            int a = (i << 4) + sload;
            As[kload][a] = atoms[(size_t)(a0 + a) * ASZ + kk + kload];
        }
        if (tid < 160) {
            int src = t0 + kk - 512 + tid;
            Bs[tid] = (src >= 0 && src < NS) ? ob[src] : 0.f;
        }
        __syncthreads();

        unsigned br[24];
#pragma unroll
        for (int q = 0; q < 6; q++) {
            float4 v = *(const float4*)&Bs[(tx << 3) + (q << 2)];
            br[q * 4 + 0] = __float_as_uint(v.x); br[q * 4 + 1] = __float_as_uint(v.y);
            br[q * 4 + 2] = __float_as_uint(v.z); br[q * 4 + 3] = __float_as_uint(v.w);
        }
#pragma unroll
        for (int k = 0; k < 16; k++) {
            ull ar2[4];
#pragma unroll
            for (int i2 = 0; i2 < 4; i2++)
                ar2[i2] = *(const ull*)&As[k][(ty << 3) + (i2 << 1)];
#pragma unroll
            for (int j = 0; j < 8; j++) {
                ull bb;
                asm("mov.b64 %0, {%1, %1};" : "=l"(bb) : "r"(br[k + j]));
#pragma unroll
                for (int i2 = 0; i2 < 4; i2++)
                    asm("fma.rn.f32x2 %0, %1, %2, %0;"
                        : "+l"(acc2[i2][j]) : "l"(ar2[i2]), "l"(bb));
            }
        }
        __syncthreads();
    }
}

// ---------------- pass 2: exact recompute of hot tiles, compact candidates ----------------
__global__ __launch_bounds__(256, 2)
void recompute_kernel(const float* __restrict__ orig, const float* __restrict__ atoms) {
    __shared__ float As[16][132];
    __shared__ float Bs[160];
    const int b = blockIdx.y;
    const float tau = g_thresh[b];
    const unsigned cnt = g_work_cnt[b];
    const int tid = threadIdx.x;
    const int tx = tid & 15, ty = tid >> 4;

    for (unsigned w = blockIdx.x; w < cnt; w += gridDim.x) {
        unsigned tile = g_work[b][w];
        int a0 = (int)(tile >> 8) << 7;          // tile = atom_blk*256 + time_blk
        int t0 = (int)(tile & 255u) << 7;
        ull acc2[4][8];
        tile_gemm(orig + (size_t)b * NS, atoms, a0, t0, tid, acc2, As, Bs);

#pragma unroll
        for (int i2 = 0; i2 < 4; i2++) {
#pragma unroll
            for (int j = 0; j < 8; j++) {
                float vlo = f32x2_lo(acc2[i2][j]);
                float vhi = f32x2_hi(acc2[i2][j]);
                int abase = a0 + (ty << 3) + (i2 << 1);
                int t = t0 + (tx << 3) + j;
                if (vlo >= tau) {
                    unsigned pos = atomicAdd(&g_cand_cnt[b], 1u);
                    if (pos < CAND_MAX) {
                        g_cand_val[b][pos] = vlo;
                        g_cand_idx[b][pos] = (unsigned)abase * (unsigned)NS + (unsigned)t;
                    }
                }
                if (vhi >= tau) {
                    unsigned pos = atomicAdd(&g_cand_cnt[b], 1u);
                    if (pos < CAND_MAX) {
                        g_cand_val[b][pos] = vhi;
                        g_cand_idx[b][pos] = (unsigned)(abase + 1) * (unsigned)NS + (unsigned)t;
                    }
                }
            }
        }
        __syncthreads();
    }
}

// ---------------- exact top-64 among candidates ----------------
__global__ void select_kernel() {
    __shared__ float rv[256];
    __shared__ int   ri[256];
    const int b = blockIdx.x, tid = threadIdx.x;
    unsigned n = g_cand_cnt[b];
    if (n > CAND_MAX) n = CAND_MAX;
    for (int it = 0; it < KSP; it++) {
        float best = NEG_INF; int bi = 0;
        for (unsigned i = tid; i < n; i += 256) {
            float v = g_cand_val[b][i];
            if (v > best) { best = v; bi = (int)i; }
        }
        rv[tid] = best; ri[tid] = bi;
        __syncthreads();
        for (int s = 128; s > 0; s >>= 1) {
            if (tid < s && rv[tid + s] > rv[tid]) { rv[tid] = rv[tid + s]; ri[tid] = ri[tid + s]; }
            __syncthreads();
        }
        if (tid == 0) {
            g_topv[b * KSP + it] = rv[0];
            g_topi[b * KSP + it] = g_cand_idx[b][ri[0]];
            g_cand_val[b][ri[0]] = NEG_INF;
        }
        __syncthreads();
    }
}

// ---------------- reconstruction: deterministic gather ----------------
__global__ void output_kernel(const float* __restrict__ atoms, float* __restrict__ out) {
    __shared__ float sv[KSP];
    __shared__ int   sa[KSP];
    __shared__ int   st[KSP];
    const int b = blockIdx.y, tid = threadIdx.x;
    if (tid < KSP) {
        sv[tid] = g_topv[b * KSP + tid];
        unsigned idx = g_topi[b * KSP + tid];
        sa[tid] = (int)(idx / (unsigned)NS);
        st[tid] = (int)(idx % (unsigned)NS);
    }
    __syncthreads();
    const int p = blockIdx.x * blockDim.x + tid;
    float acc = 0.f;
#pragma unroll 8
    for (int j = 0; j < KSP; j++) {
        int o = p - st[j];
        if ((unsigned)o < (unsigned)ASZ) acc += atoms[(size_t)sa[j] * ASZ + o] * sv[j];
    }
    out[(size_t)b * NS + p] = acc;
}

// ---------------- launch ----------------
extern "C" void kernel_launch(void* const* d_in, const int* in_sizes, int n_in,
                              void* d_out, int out_size) {
    const float* orig  = (const float*)d_in[0];
    const float* atoms = (const float*)d_in[1];
    if (n_in >= 2 && in_sizes[0] == NA * ASZ) {   // defensive operand-order check
        const float* t = orig; orig = atoms; atoms = t;
    }
    float* out = (float*)d_out;

    init_kernel<<<1, 32>>>();
    conv_atoms_kernel<<<(NA * ASZ + 255) / 256, 256>>>(atoms);
    build_sig_kernel<<<(NB * 16 * SIG_LEN + 255) / 256, 256>>>(orig);
    corr_tc_kernel<<<dim3(256, 16, NB), 256>>>();
    thresh_kernel<<<NB, 256>>>();
    worklist_kernel<<<NB, 256>>>();
    recompute_kernel<<<dim3(256, NB), 256>>>(orig, atoms);
    select_kernel<<<NB, 256>>>();
    output_kernel<<<dim3(NS / 256, NB), 256>>>(atoms, out);
}